// round 17
// baseline (speedup 1.0000x reference)
#include <cuda_runtime.h>
#include <cuda_bf16.h>
#include <cstdint>

typedef unsigned long long ull;

#define TT 4
#define BB 2
#define NW 64
#define WS 128
#define CC 256
#define HH 8
#define HD 32
#define NQKV 768
#define NTOK (TT * BB * NW * WS)      // 65536 rows

// ---------------- scratch (device globals; no allocation allowed) -------------
__device__ float          g_region[BB * NW * CC];
__device__ int            g_idx[BB * NW * 4];
__device__ unsigned       g_qbits[TT * BB * NW * WS * HH];
__device__ unsigned       g_kbits[TT * BB * NW * HH * HD * 4];
__device__ unsigned       g_vbits[TT * BB * NW * HH * HD * 4];
__device__ float          g_attn[TT * BB * NW * WS * CC];     // 64 MB
__device__ __nv_bfloat16  g_xh[NTOK * CC];                    // 33.5 MB  bf16(x)
__device__ __nv_bfloat16  g_wqh[CC * NQKV];                   // bf16(Wqkv)
__device__ float          g_wT[NQKV * CC];                    // Wqkv^T fp32 [col][k]

// (t,b,n,s) -> element offset of the row in x / out  (windowize mapping)
__device__ __forceinline__ int win_row_off(int t, int b, int n, int s) {
    int iwt = n >> 4, iwh = (n >> 2) & 3, iww = n & 3;
    int ipt = s >> 6, iph = (s >> 3) & 7, ipw = s & 7;
    int lt = iwt * 2 + ipt;
    int lh = iwh * 8 + iph;
    int lw = iww * 8 + ipw;
    return ((((t * BB + b) * 8 + lt) * 32 + lh) * 32 + lw) * CC;
}

// ======================= helpers ========================
__device__ __forceinline__ unsigned s2u(const void* p) {
    unsigned r;
    asm("{ .reg .u64 t; cvta.to.shared.u64 t, %1; cvt.u32.u64 %0, t; }"
        : "=r"(r) : "l"(p));
    return r;
}
// mma.sync m16n8k16 bf16 (baseline PTX, compiles for plain sm_103)
__device__ __forceinline__ void mma_bf16(float* c, const unsigned* a, const unsigned* b) {
    asm volatile(
        "mma.sync.aligned.m16n8k16.row.col.f32.bf16.bf16.f32 "
        "{%0,%1,%2,%3}, {%4,%5,%6,%7}, {%8,%9}, {%0,%1,%2,%3};"
        : "+f"(c[0]), "+f"(c[1]), "+f"(c[2]), "+f"(c[3])
        : "r"(a[0]), "r"(a[1]), "r"(a[2]), "r"(a[3]), "r"(b[0]), "r"(b[1]));
}
__device__ __forceinline__ void ldsm_x4(unsigned* r, unsigned addr) {
    asm volatile("ldmatrix.sync.aligned.m8n8.x4.shared.b16 {%0,%1,%2,%3}, [%4];"
        : "=r"(r[0]), "=r"(r[1]), "=r"(r[2]), "=r"(r[3]) : "r"(addr));
}
__device__ __forceinline__ void ldsm_x2_t(unsigned* r, unsigned addr) {
    asm volatile("ldmatrix.sync.aligned.m8n8.x2.trans.shared.b16 {%0,%1}, [%2];"
        : "=r"(r[0]), "=r"(r[1]) : "r"(addr));
}
// f32x2 packed-FMA helpers for the (proven) FFMA proj kernel
__device__ __forceinline__ ull dupf(float a) {
    ull r; unsigned u = __float_as_uint(a);
    asm("mov.b64 %0, {%1, %1};" : "=l"(r) : "r"(u));
    return r;
}
__device__ __forceinline__ void fma2(ull& d, ull a, ull b) {
    asm("fma.rn.f32x2 %0, %1, %2, %0;" : "+l"(d) : "l"(a), "l"(b));
}
__device__ __forceinline__ float lo32(ull v) { return __uint_as_float((unsigned)v); }
__device__ __forceinline__ float hi32(ull v) { return __uint_as_float((unsigned)(v >> 32)); }

// smem layout for QKV MMA kernel (hi tiles only)
// sA: [128 rows][72 bf16] (64 data + 8 pad) = 18432 B
// sB: [64 k-rows][136 bf16] (128 data + 8 pad) = 17408 B
#define OFF_AH 0u
#define OFF_BH 18432u
#define QKV_SMEM 36864

// ---------------- 0a) fp32 -> bf16 conversion --------------------------------
__global__ void convert_hi_kernel(const float* __restrict__ in,
                                  __nv_bfloat16* __restrict__ h, int n4) {
    int i = blockIdx.x * blockDim.x + threadIdx.x;
    if (i >= n4) return;
    float4 v = ((const float4*)in)[i];
    ull hh = (ull)__bfloat16_as_ushort(__float2bfloat16(v.x))
           | ((ull)__bfloat16_as_ushort(__float2bfloat16(v.y)) << 16)
           | ((ull)__bfloat16_as_ushort(__float2bfloat16(v.z)) << 32)
           | ((ull)__bfloat16_as_ushort(__float2bfloat16(v.w)) << 48);
    ((ull*)h)[i] = hh;
}
// ---------------- 0b) Wqkv transpose (fp32) for guard recompute --------------
__global__ void transpose_w_kernel(const float* __restrict__ W) {
    int col = blockIdx.x;     // 0..767
    int k = threadIdx.x;      // 0..255
    g_wT[col * CC + k] = W[(size_t)k * NQKV + col];
}

// ---------------- 1) region sums (round-3 proven) ----------------------------
__global__ void region_kernel(const float* __restrict__ x) {
    int b = blockIdx.x >> 6, n = blockIdx.x & 63;
    int c = threadIdx.x;
    float acc = 0.f;
    for (int t = 0; t < TT; ++t) {
#pragma unroll 8
        for (int s = 0; s < WS; ++s)
            acc += x[win_row_off(t, b, n, s) + c];
    }
    g_region[(b * NW + n) * CC + c] = acc;
}

// ---------------- 2) scores + top-4 (round-3 proven) -------------------------
__global__ void topk_kernel() {
    int b = blockIdx.x;
    __shared__ float sc[64][65];
    int tid = threadIdx.x;
    for (int p = tid; p < 64 * 64; p += 256) {
        int i = p >> 6, j = p & 63;
        const float4* ri = (const float4*)&g_region[(b * NW + i) * CC];
        const float4* rj = (const float4*)&g_region[(b * NW + j) * CC];
        float a0 = 0.f, a1 = 0.f, a2 = 0.f, a3 = 0.f;
#pragma unroll 8
        for (int c = 0; c < CC / 4; ++c) {
            float4 u = ri[c], w = rj[c];
            a0 += u.x * w.x; a1 += u.y * w.y; a2 += u.z * w.z; a3 += u.w * w.w;
        }
        sc[i][j] = (a0 + a1) + (a2 + a3);
    }
    __syncthreads();
    if (tid < 64) {
        ull chosen = 0;
        for (int p = 0; p < 4; ++p) {
            float best = -1e30f; int bj = 0;
            for (int j = 0; j < 64; ++j) {
                if (!((chosen >> j) & 1ULL) && sc[tid][j] > best) { best = sc[tid][j]; bj = j; }
            }
            chosen |= 1ULL << bj;
            g_idx[(b * NW + tid) * 4 + p] = bj;
        }
    }
}

// ---------------- 3) QKV GEMM: bf16 MMA + fp32-serial guard + bitpack --------
__global__ __launch_bounds__(256, 2)
void qkv_mma_kernel(const float* __restrict__ x, const float* __restrict__ bias) {
    extern __shared__ char sm[];
    unsigned sb = s2u(sm);
    __shared__ float sbias[128];
    __shared__ int srowoff[128];
    int tid = threadIdx.x, lid = tid & 31, wid = tid >> 5;
    int ntile = blockIdx.x;           // 0..5  (128-wide output tiles of 768)
    int tbn = blockIdx.y;
    int t = tbn >> 7, b = (tbn >> 6) & 1, n = tbn & 63;
    int ncol0 = ntile * 128;

    if (tid < 128) {
        sbias[tid] = bias[ncol0 + tid];
        srowoff[tid] = win_row_off(t, b, n, tid);
    }
    __syncthreads();

    int arow = tid >> 1, ahalf = tid & 1;
    int aoff = srowoff[arow] + ahalf * 32;

    int m0 = (wid & 3) * 32, n0 = (wid >> 2) * 64;
    float acc[2][8][4];
#pragma unroll
    for (int i = 0; i < 2; ++i)
#pragma unroll
        for (int j = 0; j < 8; ++j)
#pragma unroll
            for (int r = 0; r < 4; ++r) acc[i][j][r] = 0.f;

    for (int kc = 0; kc < 4; ++kc) {
        int kt = kc * 64;
        // stage A (128x64 bf16)
        {
            const uint4* gh = (const uint4*)(g_xh + aoff + kt);
            unsigned so = (unsigned)arow * 144u + (unsigned)ahalf * 64u;
#pragma unroll
            for (int i = 0; i < 4; ++i)
                *(uint4*)(sm + OFF_AH + so + i * 16) = gh[i];
        }
        // stage B (64k x 128n bf16)
#pragma unroll
        for (int i = 0; i < 4; ++i) {
            int lin = tid + 256 * i;
            int k = lin >> 4, seg = lin & 15;
            size_t gb = (size_t)(kt + k) * NQKV + ncol0 + seg * 8;
            *(uint4*)(sm + OFF_BH + (unsigned)k * 272u + (unsigned)seg * 16u) =
                *(const uint4*)(g_wqh + gb);
        }
        __syncthreads();
#pragma unroll
        for (int ks = 0; ks < 4; ++ks) {
            int kb = ks * 16;
            unsigned ah[2][4];
#pragma unroll
            for (int mt = 0; mt < 2; ++mt) {
                unsigned ra = (unsigned)(m0 + mt * 16 + (lid & 15)) * 144u
                            + (unsigned)(kb + ((lid >> 4) << 3)) * 2u;
                ldsm_x4(ah[mt], sb + OFF_AH + ra);
            }
#pragma unroll
            for (int nt = 0; nt < 8; ++nt) {
                unsigned rb = (unsigned)(kb + (lid & 15)) * 272u
                            + (unsigned)(n0 + nt * 8) * 2u;
                unsigned bh[2];
                ldsm_x2_t(bh, sb + OFF_BH + rb);
#pragma unroll
                for (int mt = 0; mt < 2; ++mt)
                    mma_bf16(acc[mt][nt], ah[mt], bh);
            }
        }
        __syncthreads();
    }

    // epilogue: bias + LIF threshold.
    // Near-threshold band -> recompute with a SERIAL fp32 FMA chain over
    // k = 0..255 in order (bit-compatible with the round-3 fp32 kernel that
    // matched the reference's spike decisions exactly). fp64 here is WRONG:
    // it resolves borderline elements to the true value, which disagrees with
    // the fp32 reference (measured: rel_err 1.69e-3 in R13/R16).
    unsigned char* tile = (unsigned char*)sm;   // [128][136] bytes
#pragma unroll
    for (int mt = 0; mt < 2; ++mt)
#pragma unroll
        for (int nt = 0; nt < 8; ++nt)
#pragma unroll
            for (int r = 0; r < 4; ++r) {
                int m = m0 + mt * 16 + (lid >> 2) + ((r >> 1) << 3);
                int col = n0 + nt * 8 + ((lid & 3) << 1) + (r & 1);
                float v = acc[mt][nt][r] + sbias[col];
                bool sp;
                if (fabsf(v - 2.0f) < 0.05f) {
                    float s = 0.f;
                    const float* xr = x + srowoff[m];
                    const float* wc = g_wT + (size_t)(ncol0 + col) * CC;
                    for (int k = 0; k < 256; ++k)
                        s = __fmaf_rn(xr[k], wc[k], s);
                    sp = ((s + sbias[col]) >= 2.0f);
                } else {
                    sp = (v >= 2.0f);
                }
                tile[m * 136 + col] = sp ? 1 : 0;
            }
    __syncthreads();

    int type = ntile >> 1, colbase = (ntile & 1) * 128;
    if (type == 0) {
        for (int w = tid; w < 512; w += 256) {
            int m = w >> 2, hh = w & 3;
            unsigned bits = 0;
#pragma unroll
            for (int d = 0; d < 32; ++d)
                bits |= ((unsigned)tile[m * 136 + hh * 32 + d]) << d;
            g_qbits[(tbn * WS + m) * HH + (colbase >> 5) + hh] = bits;
        }
    } else {
        unsigned* dst = (type == 1) ? g_kbits : g_vbits;
        for (int w = tid; w < 512; w += 256) {
            int nl = w >> 2, sw = w & 3;
            unsigned bits = 0;
#pragma unroll
            for (int j = 0; j < 32; ++j)
                bits |= ((unsigned)tile[(sw * 32 + j) * 136 + nl]) << j;
            int col = colbase + nl;
            dst[((tbn * HH + (col >> 5)) * HD + (col & 31)) * 4 + sw] = bits;
        }
    }
}

// ---------------- 4) linear attention over bit-packed spikes -----------------
__global__ void attn_kernel() {
    int g = blockIdx.x;                        // ((t*B+b)*NW+n)*HH+h
    int h = g & 7, n = (g >> 3) & 63, b = (g >> 9) & 1, t = g >> 10;
    int tid = threadIdx.x;

    __shared__ unsigned kb[4 * 32 * 4];
    __shared__ unsigned vb[4 * 32 * 4];
    __shared__ unsigned short kvs[32][32];
    __shared__ unsigned short ks[32];
    __shared__ int widx[4];

    if (tid < 4) widx[tid] = g_idx[(b * NW + n) * 4 + tid];
    __syncthreads();

    for (int i = tid; i < 512; i += 256) {
        int win = i >> 7, r = i & 127;
        int base = (((t * BB + b) * NW + widx[win]) * HH + h) * 128;
        kb[win * 128 + r] = g_kbits[base + r];
        vb[win * 128 + r] = g_vbits[base + r];
    }
    __syncthreads();

    for (int p = tid; p < 1024; p += 256) {
        int d = p >> 5, e = p & 31;
        const ull* kb8 = (const ull*)(kb + d * 4);
        const ull* vb8 = (const ull*)(vb + e * 4);
        int s = 0;
#pragma unroll
        for (int win = 0; win < 4; ++win) {
            s += __popcll(kb8[win * 64 + 0] & vb8[win * 64 + 0]);
            s += __popcll(kb8[win * 64 + 1] & vb8[win * 64 + 1]);
        }
        kvs[d][e] = (unsigned short)s;
    }
    if (tid < 32) {
        const ull* kb8 = (const ull*)(kb + tid * 4);
        int s = 0;
#pragma unroll
        for (int win = 0; win < 4; ++win)
            s += __popcll(kb8[win * 64 + 0]) + __popcll(kb8[win * 64 + 1]);
        ks[tid] = (unsigned short)s;
    }
    __syncthreads();

    int s_ = tid & 127, half = tid >> 7;
    unsigned qm = g_qbits[(((t * BB + b) * NW + n) * WS + s_) * HH + h];
    float D = 0.f;
    {
        unsigned m = qm;
        while (m) { int d = __ffs(m) - 1; m &= m - 1; D += (float)ks[d]; }
    }
    float Dp = D + 1e-6f;
    int orow = ((((t * BB + b) * NW + n) * WS + s_) * CC) + h * HD + half * 16;
#pragma unroll
    for (int e = 0; e < 16; ++e) {
        int ee = half * 16 + e;
        float num = 0.f;
        unsigned m = qm;
        while (m) { int d = __ffs(m) - 1; m &= m - 1; num += (float)kvs[d][ee]; }
        g_attn[orow + e] = num / Dp;
    }
}

// ---------------- 5) proj GEMM (round-3 proven f32x2 FFMA) -------------------
__global__ __launch_bounds__(256, 2)
void proj_kernel(const float* __restrict__ Wp, const float* __restrict__ bp,
                 float* __restrict__ out) {
    int tbn = blockIdx.x;
    int t = tbn >> 7, b = (tbn >> 6) & 1, n = tbn & 63;
    int ntile = blockIdx.y * 128;
    const float* A = g_attn + (size_t)tbn * WS * CC;

    __shared__ __align__(16) float s_As[128 * 36];
    __shared__ __align__(16) float s_Bs[32 * 132];
    __shared__ int ooff[128];

    int tid = threadIdx.x;
    int tx = tid & 15, ty = tid >> 4;
    int m0 = ty * 8, n0 = tx * 8;

    if (tid < 128) ooff[tid] = win_row_off(t, b, n, tid);
    __syncthreads();

    ull acc[8][4];
#pragma unroll
    for (int i = 0; i < 8; ++i)
#pragma unroll
        for (int p = 0; p < 4; ++p) acc[i][p] = 0ULL;

    for (int kt = 0; kt < CC; kt += 32) {
#pragma unroll
        for (int i = 0; i < 4; ++i) {
            int lin = tid + 256 * i;
            int r = lin >> 3, kq = lin & 7;
            float4 v = *(const float4*)(A + r * CC + kt + kq * 4);
            *(float4*)&s_As[r * 36 + kq * 4] = v;
        }
#pragma unroll
        for (int i = 0; i < 4; ++i) {
            int lin = tid + 256 * i;
            int kk = lin >> 5, nq = lin & 31;
            float4 v = *(const float4*)(Wp + (kt + kk) * CC + ntile + nq * 4);
            *(float4*)&s_Bs[kk * 132 + nq * 4] = v;
        }
        __syncthreads();
#pragma unroll
        for (int k4 = 0; k4 < 8; ++k4) {
            float4 a4[8];
#pragma unroll
            for (int i = 0; i < 8; ++i)
                a4[i] = *(const float4*)&s_As[(m0 + i) * 36 + k4 * 4];
#pragma unroll
            for (int kk = 0; kk < 4; ++kk) {
                ulonglong2 bA = *(const ulonglong2*)&s_Bs[(k4 * 4 + kk) * 132 + n0];
                ulonglong2 bB = *(const ulonglong2*)&s_Bs[(k4 * 4 + kk) * 132 + n0 + 4];
#pragma unroll
                for (int i = 0; i < 8; ++i) {
                    float av = (kk == 0) ? a4[i].x : (kk == 1) ? a4[i].y
                             : (kk == 2) ? a4[i].z : a4[i].w;
                    ull ap = dupf(av);
                    fma2(acc[i][0], ap, bA.x);
                    fma2(acc[i][1], ap, bA.y);
                    fma2(acc[i][2], ap, bB.x);
                    fma2(acc[i][3], ap, bB.y);
                }
            }
        }
        __syncthreads();
    }

    float4 bv0 = *(const float4*)(bp + ntile + n0);
    float4 bv1 = *(const float4*)(bp + ntile + n0 + 4);
#pragma unroll
    for (int i = 0; i < 8; ++i) {
        float4 o0, o1;
        o0.x = lo32(acc[i][0]) + bv0.x;  o0.y = hi32(acc[i][0]) + bv0.y;
        o0.z = lo32(acc[i][1]) + bv0.z;  o0.w = hi32(acc[i][1]) + bv0.w;
        o1.x = lo32(acc[i][2]) + bv1.x;  o1.y = hi32(acc[i][2]) + bv1.y;
        o1.z = lo32(acc[i][3]) + bv1.z;  o1.w = hi32(acc[i][3]) + bv1.w;
        int ro = ooff[m0 + i] + ntile + n0;
        *(float4*)(out + ro)     = o0;
        *(float4*)(out + ro + 4) = o1;
    }
}

// ---------------------------------------------------------------------------
extern "C" void kernel_launch(void* const* d_in, const int* in_sizes, int n_in,
                              void* d_out, int out_size) {
    const float* x     = (const float*)d_in[0];
    const float* Wqkv  = (const float*)d_in[1];
    const float* bqkv  = (const float*)d_in[2];
    const float* Wproj = (const float*)d_in[3];
    const float* bproj = (const float*)d_in[4];
    float* out = (float*)d_out;

    cudaFuncSetAttribute(qkv_mma_kernel, cudaFuncAttributeMaxDynamicSharedMemorySize, QKV_SMEM);

    __nv_bfloat16 *xh, *wqh;
    cudaGetSymbolAddress((void**)&xh,  g_xh);
    cudaGetSymbolAddress((void**)&wqh, g_wqh);

    convert_hi_kernel<<<(NTOK * CC / 4 + 255) / 256, 256>>>(x, xh, NTOK * CC / 4);
    convert_hi_kernel<<<(CC * NQKV / 4 + 255) / 256, 256>>>(Wqkv, wqh, CC * NQKV / 4);
    transpose_w_kernel<<<NQKV, 256>>>(Wqkv);

    region_kernel<<<BB * NW, 256>>>(x);
    topk_kernel<<<BB, 256>>>();

    qkv_mma_kernel<<<dim3(6, TT * BB * NW), 256, QKV_SMEM>>>(x, bqkv);
    attn_kernel<<<TT * BB * NW * HH, 256>>>();
    proj_kernel<<<dim3(TT * BB * NW, 2), 256>>>(Wproj, bproj, out);
}